// round 4
// baseline (speedup 1.0000x reference)
#include <cuda_runtime.h>
#include <cuda_fp16.h>
#include <math.h>
#include <stdint.h>

#define C_DIM 512
#define B_DIM 64
#define N_DIM 1024
#define M_AG  16
#define R_DIM (B_DIM * N_DIM)   // 65536
#define K2    1024               // virtual K: [hi|lo] for X, [w|w] for W

// ---------------- scratch (allocation-free) ----------------
__device__ float g_Q[(size_t)R_DIM * C_DIM];
__device__ float g_K[(size_t)R_DIM * C_DIM];
__device__ float g_V[(size_t)R_DIM * C_DIM];
__device__ float g_A[(size_t)B_DIM * M_AG * C_DIM];
__device__ float g_AF[(size_t)B_DIM * M_AG * C_DIM];
__device__ __half g_Xs[(size_t)R_DIM * K2];     // [ hi(512) | lo(512) ]
__device__ __half g_Ats[(size_t)R_DIM * K2];
__device__ __half g_Ws[(size_t)4 * C_DIM * K2]; // [ w(512) | w(512) ] per row

__device__ __forceinline__ uint32_t smem_u32(const void* p) {
    return (uint32_t)__cvta_generic_to_shared(p);
}
__device__ __forceinline__ void cp_async16(uint32_t s, const void* g) {
    asm volatile("cp.async.cg.shared.global [%0], [%1], 16;" :: "r"(s), "l"(g));
}
__device__ __forceinline__ void ldmatrix_x4(uint32_t* r, uint32_t addr) {
    asm volatile("ldmatrix.sync.aligned.m8n8.x4.shared.b16 {%0,%1,%2,%3}, [%4];"
                 : "=r"(r[0]), "=r"(r[1]), "=r"(r[2]), "=r"(r[3]) : "r"(addr));
}
__device__ __forceinline__ void mma16816(float* c, const uint32_t* a, uint32_t b0, uint32_t b1) {
    asm volatile(
        "mma.sync.aligned.m16n8k16.row.col.f32.f16.f16.f32 "
        "{%0,%1,%2,%3}, {%4,%5,%6,%7}, {%8,%9}, {%0,%1,%2,%3};"
        : "+f"(c[0]), "+f"(c[1]), "+f"(c[2]), "+f"(c[3])
        : "r"(a[0]), "r"(a[1]), "r"(a[2]), "r"(a[3]), "r"(b0), "r"(b1));
}

// ================= fp32 -> fp16 splits =================
// X: dst row 1024: [0,512)=fp16(x), [512,1024)=fp16(x - hi)
__global__ void split_x_kernel(const float* __restrict__ src, __half* __restrict__ dst, int nq)
{
    int i = blockIdx.x * blockDim.x + threadIdx.x;
    if (i >= nq) return;
    int row = i >> 7;
    int c4  = i & 127;
    float4 v = reinterpret_cast<const float4*>(src)[i];
    __half h0 = __float2half(v.x), h1 = __float2half(v.y);
    __half h2 = __float2half(v.z), h3 = __float2half(v.w);
    __half l0 = __float2half(v.x - __half2float(h0));
    __half l1 = __float2half(v.y - __half2float(h1));
    __half l2 = __float2half(v.z - __half2float(h2));
    __half l3 = __float2half(v.w - __half2float(h3));
    uint2 ph, pl;
    ph.x = (uint32_t)__half_as_ushort(h0) | ((uint32_t)__half_as_ushort(h1) << 16);
    ph.y = (uint32_t)__half_as_ushort(h2) | ((uint32_t)__half_as_ushort(h3) << 16);
    pl.x = (uint32_t)__half_as_ushort(l0) | ((uint32_t)__half_as_ushort(l1) << 16);
    pl.y = (uint32_t)__half_as_ushort(l2) | ((uint32_t)__half_as_ushort(l3) << 16);
    *reinterpret_cast<uint2*>(dst + (size_t)row * K2 + c4 * 4)       = ph;
    *reinterpret_cast<uint2*>(dst + (size_t)row * K2 + 512 + c4 * 4) = pl;
}

// W: dst row 1024: both halves = fp16(w)
__global__ void dup_w_kernel(const float* __restrict__ src, __half* __restrict__ dst, int nq)
{
    int i = blockIdx.x * blockDim.x + threadIdx.x;
    if (i >= nq) return;
    int row = i >> 7;
    int c4  = i & 127;
    float4 v = reinterpret_cast<const float4*>(src)[i];
    uint2 p;
    p.x = (uint32_t)__half_as_ushort(__float2half(v.x)) | ((uint32_t)__half_as_ushort(__float2half(v.y)) << 16);
    p.y = (uint32_t)__half_as_ushort(__float2half(v.z)) | ((uint32_t)__half_as_ushort(__float2half(v.w)) << 16);
    *reinterpret_cast<uint2*>(dst + (size_t)row * K2 + c4 * 4)       = p;
    *reinterpret_cast<uint2*>(dst + (size_t)row * K2 + 512 + c4 * 4) = p;
}

// ================= mma.sync fp16 GEMM (K=1024 virtual) =================
// CTA tile 128x128, BK=64, 3-stage cp.async, 4 warps (2x2), warp tile 64x64.
#define GITERS  16      // 1024 / 64
#define GSTAGES 3
#define STG_BYTES 32768
#define GEMM_SMEM (GSTAGES * STG_BYTES)   // 96 KB

__global__ __launch_bounds__(128, 2)
void gemm_mma(const __half* __restrict__ Xs, const __half* __restrict__ Ws,
              const float* __restrict__ bias, float* __restrict__ Y)
{
    extern __shared__ char smem[];
    const uint32_t sb = smem_u32(smem);
    const int t   = threadIdx.x;
    const int L   = t & 31;
    const int wid = t >> 5;
    const int r0  = blockIdx.y * 128;
    const int n0  = blockIdx.x * 128;
    const int wm  = (wid & 1) * 64;
    const int wn  = (wid >> 1) * 64;

    // load mapping: thread t loads full 128B row t of X tile and of W tile
    const uint32_t ld_mask = (uint32_t)(t & 7) << 4;

    float acc[4][8][4];
#pragma unroll
    for (int m = 0; m < 4; m++)
#pragma unroll
        for (int n = 0; n < 8; n++)
#pragma unroll
            for (int k = 0; k < 4; k++) acc[m][n][k] = 0.f;

#define LOAD_STAGE(I)                                                                 \
    do {                                                                              \
        const int s_  = (I) % GSTAGES;                                                \
        const int ko_ = (I) * 64;                                                     \
        const __half* gx_ = Xs + (size_t)(r0 + t) * K2 + ko_;                         \
        const __half* gw_ = Ws + (size_t)(n0 + t) * K2 + ko_;                         \
        const uint32_t base_ = sb + s_ * STG_BYTES + (uint32_t)t * 128u;              \
        _Pragma("unroll")                                                             \
        for (int j = 0; j < 8; j++) {                                                 \
            uint32_t o_ = ((uint32_t)(j * 16)) ^ ld_mask;                             \
            cp_async16(base_ + o_,         gx_ + j * 8);                              \
            cp_async16(base_ + 16384 + o_, gw_ + j * 8);                              \
        }                                                                             \
        asm volatile("cp.async.commit_group;" ::: "memory");                          \
    } while (0)

    LOAD_STAGE(0);
    LOAD_STAGE(1);

    const int a_row0 = wm + (L & 15);
    const int a_colx = ((L >> 4) & 1) * 16;
    const int b_row0 = wn + (L & 7) + ((L >> 4) & 1) * 8;
    const int b_colx = ((L >> 3) & 1) * 16;

#pragma unroll 1
    for (int i = 0; i < GITERS; i++) {
        if (i < GITERS - 1)
            asm volatile("cp.async.wait_group 1;" ::: "memory");
        else
            asm volatile("cp.async.wait_group 0;" ::: "memory");
        __syncthreads();

        if (i + 2 < GITERS) LOAD_STAGE(i + 2);

        const uint32_t stX = sb + (i % GSTAGES) * STG_BYTES;
        const uint32_t stW = stX + 16384;

#pragma unroll
        for (int ks = 0; ks < 4; ks++) {
            uint32_t a[4][4];
#pragma unroll
            for (int mt = 0; mt < 4; mt++) {
                int row = a_row0 + mt * 16;
                uint32_t off = (uint32_t)(row * 128 + ks * 32 + a_colx);
                off ^= (uint32_t)(row & 7) << 4;
                ldmatrix_x4(a[mt], stX + off);
            }
            uint32_t bf[4][4];
#pragma unroll
            for (int p = 0; p < 4; p++) {
                int rn = b_row0 + p * 16;
                uint32_t off = (uint32_t)(rn * 128 + ks * 32 + b_colx);
                off ^= (uint32_t)(rn & 7) << 4;
                ldmatrix_x4(bf[p], stW + off);
            }
#pragma unroll
            for (int mt = 0; mt < 4; mt++)
#pragma unroll
                for (int nt = 0; nt < 8; nt++)
                    mma16816(acc[mt][nt], a[mt], bf[nt >> 1][(nt & 1) * 2], bf[nt >> 1][(nt & 1) * 2 + 1]);
        }
    }

    // epilogue
    const int g  = L >> 2;
    const int cq = (L & 3) * 2;
#pragma unroll
    for (int mt = 0; mt < 4; mt++) {
        const int r = r0 + wm + mt * 16 + g;
#pragma unroll
        for (int nt = 0; nt < 8; nt++) {
            const int col = n0 + wn + nt * 8 + cq;
            const float b0 = __ldg(&bias[col]);
            const float b1 = __ldg(&bias[col + 1]);
            float2 o0 = make_float2(acc[mt][nt][0] + b0, acc[mt][nt][1] + b1);
            float2 o1 = make_float2(acc[mt][nt][2] + b0, acc[mt][nt][3] + b1);
            *reinterpret_cast<float2*>(Y + (size_t)r * C_DIM + col)       = o0;
            *reinterpret_cast<float2*>(Y + (size_t)(r + 8) * C_DIM + col) = o1;
        }
    }
#undef LOAD_STAGE
}

// ---------------- pooling ----------------
__global__ void pool_kernel(const float* __restrict__ Q, float* __restrict__ A)
{
    int bm = blockIdx.x;
    int c  = threadIdx.x;
    const float* base = Q + (size_t)bm * 64 * C_DIM + c;
    float s = 0.f;
#pragma unroll 8
    for (int t = 0; t < 64; t++) s += base[(size_t)t * C_DIM];
    A[(size_t)bm * C_DIM + c] = s * (1.0f / 64.0f);
}

// ---------------- agent features ----------------
__global__ __launch_bounds__(256)
void agent_features_kernel(const float* __restrict__ A, const float* __restrict__ Kmat,
                           const float* __restrict__ V, float* __restrict__ AF)
{
    __shared__ float a_s[C_DIM];
    __shared__ float p_s[N_DIM];
    __shared__ float red[256];

    const int bm  = blockIdx.x;
    const int b   = bm >> 4;
    const int tid = threadIdx.x;
    const float scale = rsqrtf((float)C_DIM);

    for (int c = tid; c < C_DIM; c += 256)
        a_s[c] = A[(size_t)bm * C_DIM + c];
    __syncthreads();

    const float* Kb = Kmat + (size_t)b * N_DIM * C_DIM;
#pragma unroll
    for (int i = 0; i < 4; i++) {
        int n = tid + i * 256;
        const float4* krow = reinterpret_cast<const float4*>(Kb + (size_t)n * C_DIM);
        float dot = 0.f;
#pragma unroll 4
        for (int c4 = 0; c4 < C_DIM / 4; c4++) {
            float4 kv = krow[c4];
            dot += a_s[c4 * 4 + 0] * kv.x + a_s[c4 * 4 + 1] * kv.y
                 + a_s[c4 * 4 + 2] * kv.z + a_s[c4 * 4 + 3] * kv.w;
        }
        p_s[n] = dot * scale;
    }
    __syncthreads();

    float lmax = -INFINITY;
#pragma unroll
    for (int i = 0; i < 4; i++) lmax = fmaxf(lmax, p_s[tid + i * 256]);
    red[tid] = lmax; __syncthreads();
    for (int s = 128; s > 0; s >>= 1) {
        if (tid < s) red[tid] = fmaxf(red[tid], red[tid + s]);
        __syncthreads();
    }
    const float mx = red[0];
    __syncthreads();

    float lsum = 0.f;
#pragma unroll
    for (int i = 0; i < 4; i++) {
        int n = tid + i * 256;
        float e = __expf(p_s[n] - mx);
        p_s[n] = e;
        lsum += e;
    }
    red[tid] = lsum; __syncthreads();
    for (int s = 128; s > 0; s >>= 1) {
        if (tid < s) red[tid] += red[tid + s];
        __syncthreads();
    }
    const float inv = 1.0f / red[0];

    const float* Vb = V + (size_t)b * N_DIM * C_DIM;
    float acc0 = 0.f, acc1 = 0.f;
    for (int n = 0; n < N_DIM; n++) {
        float p = p_s[n];
        const float* vrow = Vb + (size_t)n * C_DIM;
        acc0 = fmaf(p, vrow[tid],        acc0);
        acc1 = fmaf(p, vrow[tid + 256],  acc1);
    }
    AF[(size_t)bm * C_DIM + tid]       = acc0 * inv;
    AF[(size_t)bm * C_DIM + tid + 256] = acc1 * inv;
}

// ---------------- agent attn (writes fp16 [hi|lo] rows) ----------------
__global__ __launch_bounds__(512)
void agent_attn_kernel(const float* __restrict__ Q, const float* __restrict__ A,
                       const float* __restrict__ AF, __half* __restrict__ Ats)
{
    __shared__ float af_s[M_AG][C_DIM];

    const int b    = blockIdx.y;
    const int n0   = blockIdx.x * 16;
    const int tid  = threadIdx.x;
    const int warp = tid >> 5;
    const int lane = tid & 31;
    const float scale = rsqrtf((float)C_DIM);

    const float* AFb = AF + (size_t)b * M_AG * C_DIM;
    for (int i = tid; i < M_AG * C_DIM; i += 512)
        (&af_s[0][0])[i] = AFb[i];
    __syncthreads();

    const int n = n0 + warp;
    const float* qrow = Q + ((size_t)b * N_DIM + n) * C_DIM;
    float q[16];
#pragma unroll
    for (int k = 0; k < 16; k++) q[k] = qrow[lane + 32 * k];

    const float* Ab = A + (size_t)b * M_AG * C_DIM;
    float lg[16];
#pragma unroll
    for (int m = 0; m < M_AG; m++) {
        const float* arow = Ab + (size_t)m * C_DIM;
        float p = 0.f;
#pragma unroll
        for (int k = 0; k < 16; k++) p = fmaf(q[k], arow[lane + 32 * k], p);
#pragma unroll
        for (int off = 16; off > 0; off >>= 1)
            p += __shfl_xor_sync(0xffffffffu, p, off);
        lg[m] = p * scale;
    }

    float mx = lg[0];
#pragma unroll
    for (int m = 1; m < M_AG; m++) mx = fmaxf(mx, lg[m]);
    float s = 0.f;
#pragma unroll
    for (int m = 0; m < M_AG; m++) { lg[m] = __expf(lg[m] - mx); s += lg[m]; }
    const float inv = 1.0f / s;

    __half* orow = Ats + ((size_t)b * N_DIM + n) * K2;
#pragma unroll
    for (int k = 0; k < 16; k++) {
        int c = lane + 32 * k;
        float o = 0.f;
#pragma unroll
        for (int m = 0; m < M_AG; m++) o = fmaf(lg[m], af_s[m][c], o);
        o *= inv;
        __half h = __float2half(o);
        orow[c]       = h;
        orow[c + 512] = __float2half(o - __half2float(h));
    }
}

// ---------------- launch ----------------
extern "C" void kernel_launch(void* const* d_in, const int* in_sizes, int n_in,
                              void* d_out, int out_size)
{
    const float* x  = (const float*)d_in[0];
    const float* Wq = (const float*)d_in[1];
    const float* bq = (const float*)d_in[2];
    const float* Wk = (const float*)d_in[3];
    const float* bk = (const float*)d_in[4];
    const float* Wv = (const float*)d_in[5];
    const float* bv = (const float*)d_in[6];
    const float* Wo = (const float*)d_in[7];
    const float* bo = (const float*)d_in[8];
    float* out = (float*)d_out;

    float *Q, *K, *V, *A, *AF;
    __half *Xs, *Ats, *Ws;
    cudaGetSymbolAddress((void**)&Q,   g_Q);
    cudaGetSymbolAddress((void**)&K,   g_K);
    cudaGetSymbolAddress((void**)&V,   g_V);
    cudaGetSymbolAddress((void**)&A,   g_A);
    cudaGetSymbolAddress((void**)&AF,  g_AF);
    cudaGetSymbolAddress((void**)&Xs,  g_Xs);
    cudaGetSymbolAddress((void**)&Ats, g_Ats);
    cudaGetSymbolAddress((void**)&Ws,  g_Ws);

    static int smem_set = 0;
    if (!smem_set) {
        cudaFuncSetAttribute(gemm_mma, cudaFuncAttributeMaxDynamicSharedMemorySize, GEMM_SMEM);
        smem_set = 1;
    }

    const size_t WSZ = (size_t)C_DIM * K2;
    const int nq_x = R_DIM * C_DIM / 4;
    const int nq_w = C_DIM * C_DIM / 4;

    split_x_kernel<<<nq_x / 256, 256>>>(x,  Xs, nq_x);
    dup_w_kernel<<<nq_w / 256, 256>>>(Wq, Ws + 0 * WSZ, nq_w);
    dup_w_kernel<<<nq_w / 256, 256>>>(Wk, Ws + 1 * WSZ, nq_w);
    dup_w_kernel<<<nq_w / 256, 256>>>(Wv, Ws + 2 * WSZ, nq_w);
    dup_w_kernel<<<nq_w / 256, 256>>>(Wo, Ws + 3 * WSZ, nq_w);

    dim3 gg(C_DIM / 128, R_DIM / 128);          // (4, 512)
    gemm_mma<<<gg, 128, GEMM_SMEM>>>(Xs, Ws + 0 * WSZ, bq, Q);
    gemm_mma<<<gg, 128, GEMM_SMEM>>>(Xs, Ws + 1 * WSZ, bk, K);
    gemm_mma<<<gg, 128, GEMM_SMEM>>>(Xs, Ws + 2 * WSZ, bv, V);

    pool_kernel<<<B_DIM * M_AG, C_DIM>>>(Q, A);
    agent_features_kernel<<<B_DIM * M_AG, 256>>>(A, K, V, AF);

    dim3 attn_grid(N_DIM / 16, B_DIM);
    agent_attn_kernel<<<attn_grid, 512>>>(Q, A, AF, Ats);

    gemm_mma<<<gg, 128, GEMM_SMEM>>>(Ats, Ws + 3 * WSZ, bo, out);
}

// round 5
// speedup vs baseline: 4.8067x; 4.8067x over previous
#include <cuda_runtime.h>
#include <math.h>
#include <stdint.h>

#define Cn 512
#define Bn 64
#define Nn 1024
#define Mn 16
#define SCALE 0.04419417382415922f   // 512^-0.5

// ---------------- scratch (allocation-free, all tiny) ----------------
__device__ float g_xp [1024 * 512];   // pooled x           [B*M, C]
__device__ float g_A  [1024 * 512];   // agents             [B*M, C]
__device__ float g_Aq [1024 * 512];   // A @ Wq             [B*M, C]
__device__ float g_Ak [1024 * 512];   // A @ Wk             [B*M, C]
__device__ float g_bqA[1024];         // bq . A[b,m]
__device__ float g_P  [64 * 16 * 1024]; // stage-2 logits -> probs
__device__ float g_xa [1024 * 512];   // P2 @ x             [B*M, C]
__device__ float g_AF [1024 * 512];   // xa @ Wv^T + bv
__device__ float g_AFo[1024 * 512];   // AF @ Wo^T

// ================= pooling: xp[bm,c] = mean_{t<64} x[bm*64+t, c] =================
__global__ void pool_x_kernel(const float* __restrict__ x, float* __restrict__ xp)
{
    int bm = blockIdx.x;
    int c  = threadIdx.x;
    const float* base = x + (size_t)bm * 64 * Cn + c;
    float s = 0.f;
#pragma unroll 8
    for (int t = 0; t < 64; t++) s += base[(size_t)t * Cn];
    xp[(size_t)bm * Cn + c] = s * (1.0f / 64.0f);
}

// ================= small NT GEMM: Y[r,n] = sum_k X[r,k] W[n,k] (+bias) =================
// R=1024, N=512, K=512. 64x64 tile, 256 thr, 4x4/thread, BK=32.
__global__ __launch_bounds__(256)
void gemm_nt64(const float* __restrict__ X, const float* __restrict__ W,
               const float* __restrict__ bias, float* __restrict__ Y)
{
    __shared__ float Xs[64][33];
    __shared__ float Ws[64][33];
    const int tid = threadIdx.x;
    const int tx = tid & 15, ty = tid >> 4;
    const int r0 = blockIdx.y * 64, n0 = blockIdx.x * 64;
    const int lr = tid >> 2, lk = (tid & 3) * 8;
    float acc[4][4] = {};

    for (int k0 = 0; k0 < Cn; k0 += 32) {
        float4 a0 = *(const float4*)&X[(size_t)(r0 + lr) * Cn + k0 + lk];
        float4 a1 = *(const float4*)&X[(size_t)(r0 + lr) * Cn + k0 + lk + 4];
        float4 b0 = *(const float4*)&W[(size_t)(n0 + lr) * Cn + k0 + lk];
        float4 b1 = *(const float4*)&W[(size_t)(n0 + lr) * Cn + k0 + lk + 4];
        Xs[lr][lk+0]=a0.x; Xs[lr][lk+1]=a0.y; Xs[lr][lk+2]=a0.z; Xs[lr][lk+3]=a0.w;
        Xs[lr][lk+4]=a1.x; Xs[lr][lk+5]=a1.y; Xs[lr][lk+6]=a1.z; Xs[lr][lk+7]=a1.w;
        Ws[lr][lk+0]=b0.x; Ws[lr][lk+1]=b0.y; Ws[lr][lk+2]=b0.z; Ws[lr][lk+3]=b0.w;
        Ws[lr][lk+4]=b1.x; Ws[lr][lk+5]=b1.y; Ws[lr][lk+6]=b1.z; Ws[lr][lk+7]=b1.w;
        __syncthreads();
#pragma unroll
        for (int k = 0; k < 32; k++) {
            float av[4], bv[4];
#pragma unroll
            for (int i = 0; i < 4; i++) av[i] = Xs[ty*4+i][k];
#pragma unroll
            for (int j = 0; j < 4; j++) bv[j] = Ws[tx*4+j][k];
#pragma unroll
            for (int i = 0; i < 4; i++)
#pragma unroll
                for (int j = 0; j < 4; j++)
                    acc[i][j] = fmaf(av[i], bv[j], acc[i][j]);
        }
        __syncthreads();
    }
#pragma unroll
    for (int i = 0; i < 4; i++) {
        const int r = r0 + ty*4 + i;
#pragma unroll
        for (int j = 0; j < 4; j++) {
            const int c = n0 + tx*4 + j;
            float o = acc[i][j];
            if (bias) o += __ldg(&bias[c]);
            Y[(size_t)r * Cn + c] = o;
        }
    }
}

// ================= small NN GEMM: Y[r,n] = sum_k A[r,k] W[k,n] =================
__global__ __launch_bounds__(256)
void gemm_nn64(const float* __restrict__ X, const float* __restrict__ W,
               float* __restrict__ Y)
{
    __shared__ float Xs[64][33];
    __shared__ float Ws[32][65];
    const int tid = threadIdx.x;
    const int tx = tid & 15, ty = tid >> 4;
    const int r0 = blockIdx.y * 64, n0 = blockIdx.x * 64;
    const int lr = tid >> 2, lk = (tid & 3) * 8;
    const int wk = tid >> 3, wn = (tid & 7) * 8;
    float acc[4][4] = {};

    for (int k0 = 0; k0 < Cn; k0 += 32) {
        float4 a0 = *(const float4*)&X[(size_t)(r0 + lr) * Cn + k0 + lk];
        float4 a1 = *(const float4*)&X[(size_t)(r0 + lr) * Cn + k0 + lk + 4];
        float4 b0 = *(const float4*)&W[(size_t)(k0 + wk) * Cn + n0 + wn];
        float4 b1 = *(const float4*)&W[(size_t)(k0 + wk) * Cn + n0 + wn + 4];
        Xs[lr][lk+0]=a0.x; Xs[lr][lk+1]=a0.y; Xs[lr][lk+2]=a0.z; Xs[lr][lk+3]=a0.w;
        Xs[lr][lk+4]=a1.x; Xs[lr][lk+5]=a1.y; Xs[lr][lk+6]=a1.z; Xs[lr][lk+7]=a1.w;
        Ws[wk][wn+0]=b0.x; Ws[wk][wn+1]=b0.y; Ws[wk][wn+2]=b0.z; Ws[wk][wn+3]=b0.w;
        Ws[wk][wn+4]=b1.x; Ws[wk][wn+5]=b1.y; Ws[wk][wn+6]=b1.z; Ws[wk][wn+7]=b1.w;
        __syncthreads();
#pragma unroll
        for (int k = 0; k < 32; k++) {
            float av[4], bv[4];
#pragma unroll
            for (int i = 0; i < 4; i++) av[i] = Xs[ty*4+i][k];
#pragma unroll
            for (int j = 0; j < 4; j++) bv[j] = Ws[k][tx*4+j];
#pragma unroll
            for (int i = 0; i < 4; i++)
#pragma unroll
                for (int j = 0; j < 4; j++)
                    acc[i][j] = fmaf(av[i], bv[j], acc[i][j]);
        }
        __syncthreads();
    }
#pragma unroll
    for (int i = 0; i < 4; i++) {
        const int r = r0 + ty*4 + i;
#pragma unroll
        for (int j = 0; j < 4; j++)
            Y[(size_t)r * Cn + n0 + tx*4 + j] = acc[i][j];
    }
}

// ================= bqA[r] = bq . A[r,:] =================
__global__ void bqa_kernel(const float* __restrict__ A, const float* __restrict__ bq,
                           float* __restrict__ bqA)
{
    const int row  = blockIdx.x * 8 + (threadIdx.x >> 5);
    const int lane = threadIdx.x & 31;
    const float* ar = A + (size_t)row * Cn;
    float s = 0.f;
#pragma unroll
    for (int k = 0; k < 16; k++) s += ar[lane + 32*k] * __ldg(&bq[lane + 32*k]);
#pragma unroll
    for (int off = 16; off > 0; off >>= 1) s += __shfl_xor_sync(0xffffffffu, s, off);
    if (lane == 0) bqA[row] = s;
}

// ================= stage-2 logits: L[b,m,n] = SCALE * Ak[b,m] . x[b,n] =================
// block: (n-chunk of 128, b). Ak[b] (16x512) resident in smem; x tiles transposed.
#define L2_SMEM (16*512*4 + 64*128*4)   // 65536
__global__ __launch_bounds__(256)
void logits2_kernel(const float* __restrict__ Ak, const float* __restrict__ x,
                    float* __restrict__ L)
{
    extern __shared__ float sm[];
    float* Ak_s = sm;               // [16][512]
    float* xs   = sm + 16*512;      // [64][128] k-major
    const int b   = blockIdx.y;
    const int n0  = blockIdx.x * 128;
    const int tid = threadIdx.x;
    const int mi  = tid >> 6;       // 0..3
    const int ni  = tid & 63;       // 0..63
    const int lnr = tid >> 1;       // token row 0..127
    const int le  = tid & 1;        // k half

    {
        const float4* src = (const float4*)(Ak + (size_t)b * 16 * Cn);
        float4* dst = (float4*)Ak_s;
        for (int i = tid; i < 2048; i += 256) dst[i] = src[i];
    }

    float acc[4][2] = {};
    for (int kt = 0; kt < 8; kt++) {
        __syncthreads();
        const float* gx = x + ((size_t)b * Nn + n0 + lnr) * Cn + kt*64 + le*32;
#pragma unroll
        for (int f = 0; f < 8; f++) {
            float4 v = *(const float4*)(gx + f*4);
            const int k = le*32 + f*4;
            xs[(k+0)*128 + lnr] = v.x;
            xs[(k+1)*128 + lnr] = v.y;
            xs[(k+2)*128 + lnr] = v.z;
            xs[(k+3)*128 + lnr] = v.w;
        }
        __syncthreads();
        const float* akb = Ak_s + (size_t)mi*4*Cn + kt*64;
#pragma unroll
        for (int k = 0; k < 64; k++) {
            float2 xv = *(const float2*)(xs + k*128 + 2*ni);
            float a0 = akb[0*Cn + k], a1 = akb[1*Cn + k];
            float a2 = akb[2*Cn + k], a3 = akb[3*Cn + k];
            acc[0][0] = fmaf(a0, xv.x, acc[0][0]); acc[0][1] = fmaf(a0, xv.y, acc[0][1]);
            acc[1][0] = fmaf(a1, xv.x, acc[1][0]); acc[1][1] = fmaf(a1, xv.y, acc[1][1]);
            acc[2][0] = fmaf(a2, xv.x, acc[2][0]); acc[2][1] = fmaf(a2, xv.y, acc[2][1]);
            acc[3][0] = fmaf(a3, xv.x, acc[3][0]); acc[3][1] = fmaf(a3, xv.y, acc[3][1]);
        }
    }
#pragma unroll
    for (int j = 0; j < 4; j++) {
        const int m = mi*4 + j;
        float2 o = make_float2(acc[j][0] * SCALE, acc[j][1] * SCALE);
        *(float2*)(L + ((size_t)b*16 + m) * Nn + n0 + 2*ni) = o;
    }
}

// ================= in-place softmax over rows of 1024 =================
__global__ __launch_bounds__(256)
void softmax_rows(float* __restrict__ L)
{
    __shared__ float red[256];
    float* row = L + (size_t)blockIdx.x * Nn;
    const int tid = threadIdx.x;
    float v[4];
    float mx = -INFINITY;
#pragma unroll
    for (int i = 0; i < 4; i++) { v[i] = row[tid + i*256]; mx = fmaxf(mx, v[i]); }
    red[tid] = mx; __syncthreads();
    for (int s = 128; s > 0; s >>= 1) {
        if (tid < s) red[tid] = fmaxf(red[tid], red[tid + s]);
        __syncthreads();
    }
    mx = red[0]; __syncthreads();
    float sum = 0.f;
#pragma unroll
    for (int i = 0; i < 4; i++) { v[i] = __expf(v[i] - mx); sum += v[i]; }
    red[tid] = sum; __syncthreads();
    for (int s = 128; s > 0; s >>= 1) {
        if (tid < s) red[tid] += red[tid + s];
        __syncthreads();
    }
    const float inv = 1.0f / red[0];
#pragma unroll
    for (int i = 0; i < 4; i++) row[tid + i*256] = v[i] * inv;
}

// ================= xa[b,m,c] = sum_n P[b,m,n] x[b,n,c] =================
// block: (c-chunk of 128, b)
__global__ __launch_bounds__(256)
void xa_kernel(const float* __restrict__ P, const float* __restrict__ x,
               float* __restrict__ xa)
{
    __shared__ float xs[64][132];
    __shared__ float ps[16][64];
    const int b   = blockIdx.y;
    const int c0  = blockIdx.x * 128;
    const int tid = threadIdx.x;
    const int mi  = tid >> 6;
    const int ci  = tid & 63;
    const int lnr = tid >> 3;          // 0..31
    float acc[4][2] = {};

    for (int nt = 0; nt < 16; nt++) {
        __syncthreads();
#pragma unroll
        for (int h = 0; h < 2; h++) {
            const int n = lnr + h*32;
            const float* gx = x + ((size_t)b * Nn + nt*64 + n) * Cn + c0;
#pragma unroll
            for (int q = 0; q < 4; q++) {
                const int cc = ((tid & 7) + q*8) * 4;
                *(float4*)(&xs[n][cc]) = *(const float4*)(gx + cc);
            }
        }
        for (int i = tid; i < 16*64; i += 256) {
            const int m = i >> 6, n = i & 63;
            ps[m][n] = P[((size_t)b*16 + m) * Nn + nt*64 + n];
        }
        __syncthreads();
#pragma unroll
        for (int n = 0; n < 64; n++) {
            float2 xv = *(const float2*)(&xs[n][2*ci]);
            float p0 = ps[mi*4+0][n], p1 = ps[mi*4+1][n];
            float p2 = ps[mi*4+2][n], p3 = ps[mi*4+3][n];
            acc[0][0] = fmaf(p0, xv.x, acc[0][0]); acc[0][1] = fmaf(p0, xv.y, acc[0][1]);
            acc[1][0] = fmaf(p1, xv.x, acc[1][0]); acc[1][1] = fmaf(p1, xv.y, acc[1][1]);
            acc[2][0] = fmaf(p2, xv.x, acc[2][0]); acc[2][1] = fmaf(p2, xv.y, acc[2][1]);
            acc[3][0] = fmaf(p3, xv.x, acc[3][0]); acc[3][1] = fmaf(p3, xv.y, acc[3][1]);
        }
    }
#pragma unroll
    for (int j = 0; j < 4; j++)
        *(float2*)(xa + ((size_t)b*16 + mi*4 + j) * Cn + c0 + 2*ci)
            = make_float2(acc[j][0], acc[j][1]);
}

// ================= final: out[b,n,:] = softmax_m(SCALE*(x.Aq + bqA)) @ AFo + bo =================
#define FIN_SMEM (2*16*512*4 + 64)
__global__ __launch_bounds__(512)
void final_kernel(const float* __restrict__ x, const float* __restrict__ Aq,
                  const float* __restrict__ bqA, const float* __restrict__ AFo,
                  const float* __restrict__ bo, float* __restrict__ out)
{
    extern __shared__ float sm[];
    float* Aq_s  = sm;            // [16][512]
    float* AFo_s = sm + 8192;     // [16][512]
    float* bqA_s = sm + 16384;    // [16]
    const int b    = blockIdx.y;
    const int n0   = blockIdx.x * 16;
    const int tid  = threadIdx.x;
    const int warp = tid >> 5;
    const int lane = tid & 31;

    for (int i = tid; i < 8192; i += 512) {
        Aq_s[i]  = Aq [(size_t)b * 8192 + i];
        AFo_s[i] = AFo[(size_t)b * 8192 + i];
    }
    if (tid < 16) bqA_s[tid] = bqA[b*16 + tid];
    __syncthreads();

    const int n = n0 + warp;
    const float* xr = x + ((size_t)b * Nn + n) * Cn;
    float q[16];
#pragma unroll
    for (int k = 0; k < 16; k++) q[k] = xr[lane + 32*k];

    float lg[16];
#pragma unroll
    for (int m = 0; m < Mn; m++) {
        const float* aq = Aq_s + m * Cn;
        float p = 0.f;
#pragma unroll
        for (int k = 0; k < 16; k++) p = fmaf(q[k], aq[lane + 32*k], p);
#pragma unroll
        for (int off = 16; off > 0; off >>= 1)
            p += __shfl_xor_sync(0xffffffffu, p, off);
        lg[m] = (p + bqA_s[m]) * SCALE;
    }

    float mx = lg[0];
#pragma unroll
    for (int m = 1; m < Mn; m++) mx = fmaxf(mx, lg[m]);
    float s = 0.f;
#pragma unroll
    for (int m = 0; m < Mn; m++) { lg[m] = __expf(lg[m] - mx); s += lg[m]; }
    const float inv = 1.0f / s;

    float* orow = out + ((size_t)b * Nn + n) * Cn;
#pragma unroll
    for (int k = 0; k < 16; k++) {
        const int c = lane + 32*k;
        float o = 0.f;
#pragma unroll
        for (int m = 0; m < Mn; m++) o = fmaf(lg[m], AFo_s[m * Cn + c], o);
        orow[c] = o * inv + __ldg(&bo[c]);
    }
}

// ================= launch =================
extern "C" void kernel_launch(void* const* d_in, const int* in_sizes, int n_in,
                              void* d_out, int out_size)
{
    const float* x  = (const float*)d_in[0];
    const float* Wq = (const float*)d_in[1];
    const float* bq = (const float*)d_in[2];
    const float* Wk = (const float*)d_in[3];
    const float* bk = (const float*)d_in[4];   // unused: drops under softmax shift-invariance
    const float* Wv = (const float*)d_in[5];
    const float* bv = (const float*)d_in[6];
    const float* Wo = (const float*)d_in[7];
    const float* bo = (const float*)d_in[8];
    float* out = (float*)d_out;
    (void)bk;

    float *xp, *A, *Aq, *Ak, *bqA, *P, *xa, *AF, *AFo;
    cudaGetSymbolAddress((void**)&xp,  g_xp);
    cudaGetSymbolAddress((void**)&A,   g_A);
    cudaGetSymbolAddress((void**)&Aq,  g_Aq);
    cudaGetSymbolAddress((void**)&Ak,  g_Ak);
    cudaGetSymbolAddress((void**)&bqA, g_bqA);
    cudaGetSymbolAddress((void**)&P,   g_P);
    cudaGetSymbolAddress((void**)&xa,  g_xa);
    cudaGetSymbolAddress((void**)&AF,  g_AF);
    cudaGetSymbolAddress((void**)&AFo, g_AFo);

    static int attr_set = 0;
    if (!attr_set) {
        cudaFuncSetAttribute(logits2_kernel, cudaFuncAttributeMaxDynamicSharedMemorySize, L2_SMEM);
        cudaFuncSetAttribute(final_kernel,   cudaFuncAttributeMaxDynamicSharedMemorySize, FIN_SMEM);
        attr_set = 1;
    }

    dim3 gsm(8, 16);   // small GEMM grid: N=512/64 x R=1024/64

    // 1. pooled x
    pool_x_kernel<<<1024, 512>>>(x, xp);
    // 2. A = xp @ Wq^T + bq
    gemm_nt64<<<gsm, 256>>>(xp, Wq, bq, A);
    // 3. Aq = A @ Wq ; Ak = A @ Wk ; bqA = A . bq
    gemm_nn64<<<gsm, 256>>>(A, Wq, Aq);
    gemm_nn64<<<gsm, 256>>>(A, Wk, Ak);
    bqa_kernel<<<128, 256>>>(A, bq, bqA);
    // 4. stage-2 logits + softmax over n
    logits2_kernel<<<dim3(8, 64), 256, L2_SMEM>>>(Ak, x, P);
    softmax_rows<<<1024, 256>>>(P);
    // 5. xa = P @ x
    xa_kernel<<<dim3(4, 64), 256>>>(P, x, xa);
    // 6. AF = xa @ Wv^T + bv ; AFo = AF @ Wo^T
    gemm_nt64<<<gsm, 256>>>(xa, Wv, bv, AF);
    gemm_nt64<<<gsm, 256>>>(AF, Wo, (const float*)nullptr, AFo);
    // 7. stage-1 softmax + combine + bo
    final_kernel<<<dim3(64, 64), 512, FIN_SMEM>>>(x, Aq, bqA, AFo, bo, out);
}

// round 6
// speedup vs baseline: 6.4679x; 1.3456x over previous
#include <cuda_runtime.h>
#include <math.h>
#include <stdint.h>

#define Cn 512
#define Bn 64
#define Nn 1024
#define Mn 16
#define SCALE 0.04419417382415922f   // 512^-0.5

// ---------------- scratch (allocation-free) ----------------
__device__ float g_xp  [1024 * 512];    // pooled x        [B*M, C]
__device__ float g_A   [1024 * 512];    // agents          [B*M, C]
__device__ float g_Aq  [1024 * 512];    // A @ Wq
__device__ float g_Ak  [1024 * 512];    // A @ Wk
__device__ float g_bqA [1024];          // bq . A
__device__ float g_bvo [512];           // Wo . bv
__device__ float g_WqT [512 * 512];
__device__ float g_WvT [512 * 512];
__device__ float g_WoT [512 * 512];
__device__ float g_WcT [512 * 512];     // (Wo@Wv)^T = WvT @ WoT
__device__ float g_L2  [64 * 16 * 1024];// stage-2 logits
__device__ float g_L1  [64 * 1024 * 16];// stage-1 logits (scaled, +bqA)
__device__ float g_xa  [1024 * 512];    // P2 @ x
__device__ float g_AFo [1024 * 512];    // xa @ WcT + bvo

__device__ __forceinline__ uint32_t smem_u32(const void* p) {
    return (uint32_t)__cvta_generic_to_shared(p);
}
__device__ __forceinline__ void cp_async16(uint32_t s, const void* g) {
    asm volatile("cp.async.cg.shared.global [%0], [%1], 16;" :: "r"(s), "l"(g));
}

// ================= batched 512x512 transpose (Wq, Wv, Wo) =================
__global__ void transpose3(const float* __restrict__ Wq, const float* __restrict__ Wv,
                           const float* __restrict__ Wo, float* __restrict__ WqT,
                           float* __restrict__ WvT, float* __restrict__ WoT)
{
    __shared__ float t[32][33];
    const float* s; float* d;
    if (blockIdx.z == 0)      { s = Wq; d = WqT; }
    else if (blockIdx.z == 1) { s = Wv; d = WvT; }
    else                      { s = Wo; d = WoT; }
    const int x  = blockIdx.x * 32 + threadIdx.x;
    const int y0 = blockIdx.y * 32 + threadIdx.y;
#pragma unroll
    for (int j = 0; j < 32; j += 8)
        t[threadIdx.y + j][threadIdx.x] = s[(size_t)(y0 + j) * Cn + x];
    __syncthreads();
    const int ox  = blockIdx.y * 32 + threadIdx.x;
    const int oy0 = blockIdx.x * 32 + threadIdx.y;
#pragma unroll
    for (int j = 0; j < 32; j += 8)
        d[(size_t)(oy0 + j) * Cn + ox] = t[threadIdx.x][threadIdx.y + j];
}

// ================= pooling =================
__global__ void pool_x_kernel(const float* __restrict__ x, float* __restrict__ xp)
{
    int bm = blockIdx.x;
    int c  = threadIdx.x;
    const float* base = x + (size_t)bm * 64 * Cn + c;
    float s = 0.f;
#pragma unroll 8
    for (int t = 0; t < 64; t++) s += base[(size_t)t * Cn];
    xp[(size_t)bm * Cn + c] = s * (1.0f / 64.0f);
}

// ================= NN GEMM: Y[r,n] = sum_k X[r,k] W[k,n] (+bias) =================
// K=512. Tile 64x64, BK=32, 3-stage cp.async, 256 thr, 4x4/thread, float4 inner.
// dual-W: blocks bx < nsplit use (W0,Y0,n0=bx*64), else (W1,Y1,n0=(bx-nsplit)*64)
#define XS_FLOATS (64 * 36)          // 2304
#define WS_FLOATS (32 * 68)          // 2176
#define STAGE_FLOATS (XS_FLOATS + WS_FLOATS)  // 4480
#define GEMM_SMEM (3 * STAGE_FLOATS * 4)      // 53760

__global__ __launch_bounds__(256)
void gemm_nn(const float* __restrict__ X, const float* __restrict__ W0,
             const float* __restrict__ W1, const float* __restrict__ bias,
             float* __restrict__ Y0, float* __restrict__ Y1, int nsplit)
{
    extern __shared__ float sm[];
    const int tid = threadIdx.x;
    const int tx = tid & 15, ty = tid >> 4;
    const int r0 = blockIdx.y * 64;
    const float* W; float* Y; int n0;
    if ((int)blockIdx.x < nsplit) { W = W0; Y = Y0; n0 = blockIdx.x * 64; }
    else                          { W = W1; Y = Y1; n0 = (blockIdx.x - nsplit) * 64; }

    const int xlr = tid >> 2, xlk = (tid & 3) * 8;
    const int wwk = tid >> 3, wwn = (tid & 7) * 8;
    const float* gX = X + (size_t)(r0 + xlr) * Cn + xlk;
    const float* gW = W + (size_t)wwk * Cn + n0 + wwn;
    const uint32_t sbase = smem_u32(sm);
    const uint32_t xdst = sbase + (uint32_t)(xlr * 36 + xlk) * 4u;
    const uint32_t wdst = sbase + (uint32_t)(XS_FLOATS + wwk * 68 + wwn) * 4u;

#define G_LOAD(ST, K0)                                                          \
    do {                                                                        \
        const uint32_t so_ = (uint32_t)(ST) * (STAGE_FLOATS * 4u);              \
        cp_async16(xdst + so_,      gX + (K0));                                 \
        cp_async16(xdst + so_ + 16, gX + (K0) + 4);                             \
        cp_async16(wdst + so_,      gW + (size_t)(K0) * Cn);                    \
        cp_async16(wdst + so_ + 16, gW + (size_t)(K0) * Cn + 4);                \
        asm volatile("cp.async.commit_group;" ::: "memory");                    \
    } while (0)

    float acc[4][4];
#pragma unroll
    for (int i = 0; i < 4; i++)
#pragma unroll
        for (int j = 0; j < 4; j++) acc[i][j] = 0.f;

    G_LOAD(0, 0);
    G_LOAD(1, 32);

#pragma unroll 1
    for (int it = 0; it < 16; it++) {
        if (it < 15) asm volatile("cp.async.wait_group 1;" ::: "memory");
        else         asm volatile("cp.async.wait_group 0;" ::: "memory");
        __syncthreads();
        if (it + 2 < 16) G_LOAD((it + 2) % 3, (it + 2) * 32);

        const float* Xst = sm + (it % 3) * STAGE_FLOATS;
        const float* Wst = Xst + XS_FLOATS;
#pragma unroll
        for (int k4 = 0; k4 < 8; k4++) {
            float aa[4][4], bb[4][4];
#pragma unroll
            for (int i = 0; i < 4; i++) {
                float4 a = *(const float4*)(Xst + (ty * 4 + i) * 36 + k4 * 4);
                aa[i][0] = a.x; aa[i][1] = a.y; aa[i][2] = a.z; aa[i][3] = a.w;
            }
#pragma unroll
            for (int q = 0; q < 4; q++) {
                float4 b = *(const float4*)(Wst + (k4 * 4 + q) * 68 + tx * 4);
                bb[q][0] = b.x; bb[q][1] = b.y; bb[q][2] = b.z; bb[q][3] = b.w;
            }
#pragma unroll
            for (int i = 0; i < 4; i++)
#pragma unroll
                for (int j = 0; j < 4; j++)
#pragma unroll
                    for (int q = 0; q < 4; q++)
                        acc[i][j] = fmaf(aa[i][q], bb[q][j], acc[i][j]);
        }
    }
#undef G_LOAD

    float4 bi = make_float4(0.f, 0.f, 0.f, 0.f);
    if (bias) bi = *(const float4*)(bias + n0 + tx * 4);
#pragma unroll
    for (int i = 0; i < 4; i++) {
        float4 o;
        o.x = acc[i][0] + bi.x; o.y = acc[i][1] + bi.y;
        o.z = acc[i][2] + bi.z; o.w = acc[i][3] + bi.w;
        *(float4*)(Y + (size_t)(r0 + ty * 4 + i) * Cn + n0 + tx * 4) = o;
    }
}

// ================= rowdot: dst[r] = src[r,:] . vec =================
__global__ void rowdot_kernel(const float* __restrict__ src, const float* __restrict__ vec,
                              float* __restrict__ dst)
{
    const int row  = blockIdx.x * 8 + (threadIdx.x >> 5);
    const int lane = threadIdx.x & 31;
    const float* sr = src + (size_t)row * Cn;
    float s = 0.f;
#pragma unroll
    for (int k = 0; k < 16; k++) s += sr[lane + 32 * k] * __ldg(&vec[lane + 32 * k]);
#pragma unroll
    for (int off = 16; off > 0; off >>= 1) s += __shfl_xor_sync(0xffffffffu, s, off);
    if (lane == 0) dst[row] = s;
}

// ================= fused logits: L1[b,n,m], L2[b,m,n] in one x pass =================
#define L12_SMEM (2 * 16 * 512 * 4 + 64 * 128 * 4 + 64)
__global__ __launch_bounds__(256)
void logits12_kernel(const float* __restrict__ Aq, const float* __restrict__ Ak,
                     const float* __restrict__ bqA, const float* __restrict__ x,
                     float* __restrict__ L1, float* __restrict__ L2)
{
    extern __shared__ float sm[];
    float* Aq_s = sm;                 // [16][512]
    float* Ak_s = sm + 8192;          // [16][512]
    float* xs   = sm + 16384;         // [64][128] k-major
    float* bq_s = sm + 24576;         // [16]
    const int b   = blockIdx.y;
    const int n0  = blockIdx.x * 128;
    const int tid = threadIdx.x;
    const int mi  = tid >> 6;         // 0..3 (m-group of 4)
    const int ni  = tid & 63;         // 2 tokens
    const int lnr = tid >> 1;         // token 0..127
    const int le  = tid & 1;          // k half

    {
        const float4* sq = (const float4*)(Aq + (size_t)b * 16 * Cn);
        const float4* sk = (const float4*)(Ak + (size_t)b * 16 * Cn);
        float4* dq = (float4*)Aq_s;
        float4* dk = (float4*)Ak_s;
        for (int i = tid; i < 2048; i += 256) { dq[i] = sq[i]; dk[i] = sk[i]; }
        if (tid < 16) bq_s[tid] = bqA[b * 16 + tid];
    }

    float acc1[4][2] = {}, acc2[4][2] = {};
    for (int kt = 0; kt < 8; kt++) {
        __syncthreads();
        const float* gx = x + ((size_t)b * Nn + n0 + lnr) * Cn + kt * 64 + le * 32;
#pragma unroll
        for (int f = 0; f < 8; f++) {
            float4 v = *(const float4*)(gx + f * 4);
            const int k = le * 32 + f * 4;
            xs[(k + 0) * 128 + lnr] = v.x;
            xs[(k + 1) * 128 + lnr] = v.y;
            xs[(k + 2) * 128 + lnr] = v.z;
            xs[(k + 3) * 128 + lnr] = v.w;
        }
        __syncthreads();
        const float* aqb = Aq_s + (size_t)mi * 4 * Cn + kt * 64;
        const float* akb = Ak_s + (size_t)mi * 4 * Cn + kt * 64;
#pragma unroll 8
        for (int k = 0; k < 64; k++) {
            float2 xv = *(const float2*)(xs + k * 128 + 2 * ni);
#pragma unroll
            for (int j = 0; j < 4; j++) {
                float aq = aqb[j * Cn + k];
                float ak = akb[j * Cn + k];
                acc1[j][0] = fmaf(aq, xv.x, acc1[j][0]);
                acc1[j][1] = fmaf(aq, xv.y, acc1[j][1]);
                acc2[j][0] = fmaf(ak, xv.x, acc2[j][0]);
                acc2[j][1] = fmaf(ak, xv.y, acc2[j][1]);
            }
        }
    }
    // L2[b,m,n] (scaled)
#pragma unroll
    for (int j = 0; j < 4; j++) {
        float2 o = make_float2(acc2[j][0] * SCALE, acc2[j][1] * SCALE);
        *(float2*)(L2 + ((size_t)b * 16 + mi * 4 + j) * Nn + n0 + 2 * ni) = o;
    }
    // L1[b,n,m] (scaled, +bqA): thread holds 4 consecutive m for tokens 2ni, 2ni+1
    {
        float4 o0, o1;
        float* p0 = (float*)&o0; float* p1 = (float*)&o1;
#pragma unroll
        for (int j = 0; j < 4; j++) {
            p0[j] = (acc1[j][0] + bq_s[mi * 4 + j]) * SCALE;
            p1[j] = (acc1[j][1] + bq_s[mi * 4 + j]) * SCALE;
        }
        *(float4*)(L1 + ((size_t)b * Nn + n0 + 2 * ni)     * 16 + mi * 4) = o0;
        *(float4*)(L1 + ((size_t)b * Nn + n0 + 2 * ni + 1) * 16 + mi * 4) = o1;
    }
}

// ================= xa = softmax_n(L2) @ x  (softmax fused) =================
#define XA_SMEM (16 * 1024 * 4 + 64 * 132 * 4)
__global__ __launch_bounds__(256)
void xa_kernel(const float* __restrict__ L2, const float* __restrict__ x,
               float* __restrict__ xa)
{
    extern __shared__ float sm[];
    float* ps = sm;            // [16][1024]
    float* xs = sm + 16384;    // [64][132]
    const int b   = blockIdx.y;
    const int c0  = blockIdx.x * 128;
    const int tid = threadIdx.x;
    const int warp = tid >> 5, lane = tid & 31;
    const int mi  = tid >> 6;
    const int ci  = tid & 63;
    const int lnr = tid >> 3;

    // softmax of L2[b] rows into ps (each warp: 2 rows)
    for (int m = warp; m < 16; m += 8) {
        const float* row = L2 + ((size_t)b * 16 + m) * Nn;
        float mx = -INFINITY;
#pragma unroll
        for (int i = 0; i < 32; i++) mx = fmaxf(mx, __ldg(row + lane + 32 * i));
#pragma unroll
        for (int off = 16; off > 0; off >>= 1)
            mx = fmaxf(mx, __shfl_xor_sync(0xffffffffu, mx, off));
        float sum = 0.f;
#pragma unroll
        for (int i = 0; i < 32; i++) {
            float e = __expf(__ldg(row + lane + 32 * i) - mx);
            ps[m * Nn + lane + 32 * i] = e;
            sum += e;
        }
#pragma unroll
        for (int off = 16; off > 0; off >>= 1)
            sum += __shfl_xor_sync(0xffffffffu, sum, off);
        const float inv = 1.0f / sum;
#pragma unroll
        for (int i = 0; i < 32; i++) ps[m * Nn + lane + 32 * i] *= inv;
    }

    float acc[4][2] = {};
    for (int nt = 0; nt < 16; nt++) {
        __syncthreads();
#pragma unroll
        for (int h = 0; h < 2; h++) {
            const int n = lnr + h * 32;
            const float* gx = x + ((size_t)b * Nn + nt * 64 + n) * Cn + c0;
#pragma unroll
            for (int q = 0; q < 4; q++) {
                const int cc = ((tid & 7) + q * 8) * 4;
                *(float4*)(xs + n * 132 + cc) = *(const float4*)(gx + cc);
            }
        }
        __syncthreads();
        const float* pb = ps + (size_t)mi * 4 * Nn + nt * 64;
#pragma unroll 8
        for (int n = 0; n < 64; n++) {
            float2 xv = *(const float2*)(xs + n * 132 + 2 * ci);
#pragma unroll
            for (int j = 0; j < 4; j++) {
                float p = pb[j * Nn + n];
                acc[j][0] = fmaf(p, xv.x, acc[j][0]);
                acc[j][1] = fmaf(p, xv.y, acc[j][1]);
            }
        }
    }
#pragma unroll
    for (int j = 0; j < 4; j++)
        *(float2*)(xa + ((size_t)b * 16 + mi * 4 + j) * Cn + c0 + 2 * ci)
            = make_float2(acc[j][0], acc[j][1]);
}

// ================= final: out[b,n,:] = softmax_m(L1[b,n,:]) @ AFo[b] + bo =================
__global__ __launch_bounds__(512)
void final_kernel(const float* __restrict__ L1, const float* __restrict__ AFo,
                  const float* __restrict__ bo, float* __restrict__ out)
{
    __shared__ float afo_s[Mn * Cn];     // 32 KB
    __shared__ float l1_s[64 * 16];      // 4 KB
    const int b    = blockIdx.y;
    const int n0   = blockIdx.x * 64;
    const int tid  = threadIdx.x;
    const int warp = tid >> 5;
    const int lane = tid & 31;

    {
        const float4* s = (const float4*)(AFo + (size_t)b * Mn * Cn);
        float4* d = (float4*)afo_s;
        for (int i = tid; i < 2048; i += 512) d[i] = s[i];
        const float4* sl = (const float4*)(L1 + ((size_t)b * Nn + n0) * 16);
        float4* dl = (float4*)l1_s;
        if (tid < 256) dl[tid] = sl[tid];
    }
    __syncthreads();

#pragma unroll
    for (int t = 0; t < 4; t++) {
        const int tok = warp * 4 + t;
        float lg[16];
#pragma unroll
        for (int m = 0; m < Mn; m++) lg[m] = l1_s[tok * 16 + m];
        float mx = lg[0];
#pragma unroll
        for (int m = 1; m < Mn; m++) mx = fmaxf(mx, lg[m]);
        float s = 0.f;
#pragma unroll
        for (int m = 0; m < Mn; m++) { lg[m] = __expf(lg[m] - mx); s += lg[m]; }
        const float inv = 1.0f / s;

        float* orow = out + ((size_t)b * Nn + n0 + tok) * Cn;
#pragma unroll
        for (int k = 0; k < 16; k++) {
            const int c = lane + 32 * k;
            float o = 0.f;
#pragma unroll
            for (int m = 0; m < Mn; m++) o = fmaf(lg[m], afo_s[m * Cn + c], o);
            orow[c] = o * inv + __ldg(&bo[c]);
        }
    }
}

// ================= launch =================
extern "C" void kernel_launch(void* const* d_in, const int* in_sizes, int n_in,
                              void* d_out, int out_size)
{
    const float* x  = (const float*)d_in[0];
    const float* Wq = (const float*)d_in[1];
    const float* bq = (const float*)d_in[2];
    const float* Wk = (const float*)d_in[3];
    const float* bk = (const float*)d_in[4];   // drops under softmax shift-invariance
    const float* Wv = (const float*)d_in[5];
    const float* bv = (const float*)d_in[6];
    const float* Wo = (const float*)d_in[7];
    const float* bo = (const float*)d_in[8];
    float* out = (float*)d_out;
    (void)bk;

    float *xp, *A, *Aq, *Ak, *bqA, *bvo, *WqT, *WvT, *WoT, *WcT, *L1, *L2, *xa, *AFo;
    cudaGetSymbolAddress((void**)&xp,  g_xp);
    cudaGetSymbolAddress((void**)&A,   g_A);
    cudaGetSymbolAddress((void**)&Aq,  g_Aq);
    cudaGetSymbolAddress((void**)&Ak,  g_Ak);
    cudaGetSymbolAddress((void**)&bqA, g_bqA);
    cudaGetSymbolAddress((void**)&bvo, g_bvo);
    cudaGetSymbolAddress((void**)&WqT, g_WqT);
    cudaGetSymbolAddress((void**)&WvT, g_WvT);
    cudaGetSymbolAddress((void**)&WoT, g_WoT);
    cudaGetSymbolAddress((void**)&WcT, g_WcT);
    cudaGetSymbolAddress((void**)&L1,  g_L1);
    cudaGetSymbolAddress((void**)&L2,  g_L2);
    cudaGetSymbolAddress((void**)&xa,  g_xa);
    cudaGetSymbolAddress((void**)&AFo, g_AFo);

    static int attr_set = 0;
    if (!attr_set) {
        cudaFuncSetAttribute(gemm_nn,        cudaFuncAttributeMaxDynamicSharedMemorySize, GEMM_SMEM);
        cudaFuncSetAttribute(logits12_kernel, cudaFuncAttributeMaxDynamicSharedMemorySize, L12_SMEM);
        cudaFuncSetAttribute(xa_kernel,      cudaFuncAttributeMaxDynamicSharedMemorySize, XA_SMEM);
        attr_set = 1;
    }

    // independent preprocessing
    transpose3<<<dim3(16, 16, 3), dim3(32, 8)>>>(Wq, Wv, Wo, WqT, WvT, WoT);
    pool_x_kernel<<<1024, 512>>>(x, xp);
    rowdot_kernel<<<64, 256>>>(Wo, bv, bvo);                       // bvo = Wo . bv
    gemm_nn<<<dim3(8, 8),  256, GEMM_SMEM>>>(WvT, WoT, WoT, nullptr, WcT, WcT, 8);  // WcT = WvT@WoT

    // main chain
    gemm_nn<<<dim3(8, 16), 256, GEMM_SMEM>>>(xp, WqT, WqT, bq, A, A, 8);            // A = xp@Wq^T + bq
    gemm_nn<<<dim3(16, 16), 256, GEMM_SMEM>>>(A, Wq, Wk, nullptr, Aq, Ak, 8);       // Aq, Ak
    rowdot_kernel<<<128, 256>>>(A, bq, bqA);                        // bqA = A . bq

    logits12_kernel<<<dim3(8, 64), 256, L12_SMEM>>>(Aq, Ak, bqA, x, L1, L2);
    xa_kernel<<<dim3(4, 64), 256, XA_SMEM>>>(L2, x, xa);
    gemm_nn<<<dim3(8, 16), 256, GEMM_SMEM>>>(xa, WcT, WcT, bvo, AFo, AFo, 8);       // AFo = xa@WcT + bvo
    final_kernel<<<dim3(16, 64), 512>>>(L1, AFo, bo, out);
}